// round 15
// baseline (speedup 1.0000x reference)
#include <cuda_runtime.h>
#include <cstdint>
#include <cstddef>

typedef unsigned long long ull;

#define BB 4096
#define TT 256
#define DD 64
#define HH 32

// ---------- packed f32x2 helpers ----------
static __device__ __forceinline__ ull pack2(float lo, float hi) {
    ull r;
    asm("mov.b64 %0, {%1, %2};" : "=l"(r) : "f"(lo), "f"(hi));
    return r;
}
static __device__ __forceinline__ void unpack2(ull v, float& lo, float& hi) {
    asm("mov.b64 {%0, %1}, %2;" : "=f"(lo), "=f"(hi) : "l"(v));
}
static __device__ __forceinline__ void ffma2(ull& acc, ull a, ull b) {
    asm("fma.rn.f32x2 %0, %1, %2, %0;" : "+l"(acc) : "l"(a), "l"(b));
}
static __device__ __forceinline__ ull addx2(ull a, ull b) {
    ull r;
    asm("add.rn.f32x2 %0, %1, %2;" : "=l"(r) : "l"(a), "l"(b));
    return r;
}
static __device__ __forceinline__ void lds_v2u64(ull& a, ull& b, uint32_t addr) {
    asm volatile("ld.shared.v2.b64 {%0, %1}, [%2];" : "=l"(a), "=l"(b) : "r"(addr) : "memory");
}
static __device__ __forceinline__ void sts_f32(uint32_t addr, float v) {
    asm volatile("st.shared.f32 [%0], %1;" :: "r"(addr), "f"(v) : "memory");
}
static __device__ __forceinline__ void sts_u64(uint32_t addr, ull v) {
    asm volatile("st.shared.b64 [%0], %1;" :: "r"(addr), "l"(v) : "memory");
}
static __device__ __forceinline__ uint32_t smem_u32(const void* p) {
    return (uint32_t)__cvta_generic_to_shared(p);
}

// 32-long matvec, h-vector broadcast from smem, 16 packed weight pairs in regs
static __device__ __forceinline__ float matvec32(uint32_t base, const ull* Wp, float bias) {
    ull a0 = 0, a1 = 0, a2 = 0, a3 = 0;
#pragma unroll
    for (int l = 0; l < 8; l++) {
        ull p0, p1;
        lds_v2u64(p0, p1, base + l * 16);
        if (l & 1) {
            ffma2(a2, p0, Wp[2 * l]);
            ffma2(a3, p1, Wp[2 * l + 1]);
        } else {
            ffma2(a0, p0, Wp[2 * l]);
            ffma2(a1, p1, Wp[2 * l + 1]);
        }
    }
    ull s = addx2(addx2(a0, a2), addx2(a1, a3));
    float lo, hi;
    unpack2(s, lo, hi);
    return bias + (lo + hi);
}

// 64-long matvec (states part of fc1): s staged in smem as 32 ull pairs
// {s[2i],s[2i+1]} broadcast-read; 32 packed W1 pairs in REGISTERS.
static __device__ __forceinline__ float matvecA(uint32_t base, const ull* W1p, float bias) {
    ull a0 = 0, a1 = 0, a2 = 0, a3 = 0;
#pragma unroll
    for (int l = 0; l < 16; l++) {
        ull p0, p1;
        lds_v2u64(p0, p1, base + l * 16);
        if (l & 1) {
            ffma2(a2, p0, W1p[2 * l]);
            ffma2(a3, p1, W1p[2 * l + 1]);
        } else {
            ffma2(a0, p0, W1p[2 * l]);
            ffma2(a1, p1, W1p[2 * l + 1]);
        }
    }
    ull s = addx2(addx2(a0, a2), addx2(a1, a3));
    float lo, hi;
    unpack2(s, lo, hi);
    return bias + (lo + hi);
}

// ============================================================================
// Fused kernel: the precompute GEMM is folded INTO the recurrence. At step t
// the warp computes A[t+2] = b1 + s_{t+2} @ W1[:64] in its stall bubbles
// (A[t+2] is recurrence-independent), eliminating the separate 176us
// precompute launch and 256MB of scratch traffic. 3-deep s pipeline:
// sp_stage holds s(t+2) (staged to smem this step), sp_next holds s(t+3)
// in flight; the LDG for s(t+4) is issued each step -> ~1 full step of
// DRAM-latency cover. Recurrence interior = R14 (2 warps/block, 2 chains
// per warp, ballot argmax, 1-step g prefetch).
// ============================================================================
__global__ void __launch_bounds__(64) recur_fused(const float* __restrict__ states,
                                                  const float* __restrict__ gumbel,
                                                  const float* __restrict__ W1,
                                                  const float* __restrict__ b1,
                                                  const float* __restrict__ W2,
                                                  const float* __restrict__ b2,
                                                  const float* __restrict__ W3,
                                                  const float* __restrict__ b3,
                                                  float* __restrict__ out) {
    __shared__ float W1c[32 * 32];                    // rows 64..95 of W1 (categorical)
    __shared__ __align__(16) float bufx[2][2][32];    // [warp][chain] h1
    __shared__ __align__(16) float bufy[2][2][32];    // h2
    __shared__ __align__(16) ull sbuf[2][2][32];      // [warp][chain] s-pairs

    int tid = threadIdx.x;
    for (int i = tid; i < 32 * 32; i += 64) W1c[i] = W1[64 * 32 + i];
    __syncthreads();

    const unsigned FULL = 0xffffffffu;
    int w = tid >> 5;
    int j = tid & 31;
    int jg = j & 7;
    unsigned gsh = (unsigned)(j & 24);  // 8 * group index

    // register-resident packed weight pairs
    ull W1p[32], W2p[16], W3p[16];
#pragma unroll
    for (int i = 0; i < 32; i++)
        W1p[i] = pack2(__ldg(&W1[(2 * i) * 32 + j]), __ldg(&W1[(2 * i + 1) * 32 + j]));
#pragma unroll
    for (int i = 0; i < 16; i++) {
        W2p[i] = pack2(__ldg(&W2[(2 * i) * 32 + j]), __ldg(&W2[(2 * i + 1) * 32 + j]));
        W3p[i] = pack2(__ldg(&W3[(2 * i) * 32 + j]), __ldg(&W3[(2 * i + 1) * 32 + j]));
    }
    float b1j = __ldg(&b1[j]);
    float b2j = __ldg(&b2[j]);
    float b3j = __ldg(&b3[j]);

    uint32_t bx[2], by[2], sb[2], bxj[2], byj[2], sbj[2];
#pragma unroll
    for (int c = 0; c < 2; c++) {
        bx[c] = smem_u32(&bufx[w][c][0]);
        by[c] = smem_u32(&bufy[w][c][0]);
        sb[c] = smem_u32(&sbuf[w][c][0]);
        bxj[c] = bx[c] + 4 * j;
        byj[c] = by[c] + 4 * j;
        sbj[c] = sb[c] + 8 * j;
    }

    const float* Sp[2];  // states for this chain: [TT][64]
    const float* Gp[2];
    float* Op[2];
    float a_cur[2], a_n1[2], g_cur[2];
    ull sp_stage[2], sp_next[2];
    int i0[2], i1[2], i2[2], i3[2];

#pragma unroll
    for (int c = 0; c < 2; c++) {
        int b = blockIdx.x * 4 + 2 * w + c;
        Sp[c] = states + ((size_t)b * TT) * 64 + 2 * j;  // lane j owns s-pair j
        size_t gbase = ((size_t)b * TT) * 32 + j;
        Gp[c] = gumbel + gbase;
        Op[c] = out + gbase;
        i0[c] = i1[c] = i2[c] = i3[c] = 0;
        g_cur[c] = Gp[c][0];
    }

    // ---- prologue: A[0], A[1]; fill s pipeline with s(2), s(3) ----
#pragma unroll
    for (int c = 0; c < 2; c++) sts_u64(sbj[c], *(const ull*)(Sp[c] + 0 * 64));
    __syncwarp();
#pragma unroll
    for (int c = 0; c < 2; c++) a_cur[c] = matvecA(sb[c], W1p, b1j);
    __syncwarp();
#pragma unroll
    for (int c = 0; c < 2; c++) sts_u64(sbj[c], *(const ull*)(Sp[c] + 1 * 64));
    __syncwarp();
#pragma unroll
    for (int c = 0; c < 2; c++) a_n1[c] = matvecA(sb[c], W1p, b1j);
#pragma unroll
    for (int c = 0; c < 2; c++) {
        sp_stage[c] = *(const ull*)(Sp[c] + 2 * 64);
        sp_next[c] = *(const ull*)(Sp[c] + 3 * 64);
    }

#pragma unroll 1
    for (int t = 0; t < TT; t++) {
        // issue next s load early: s(t+4), clamped (redundant tail loads OK)
        int t4 = t + 4;
        if (t4 > TT - 1) t4 = TT - 1;

        // 1-step gumbel prefetch
        float g_n[2] = {0.f, 0.f};
        if (t + 1 < TT) {
#pragma unroll
            for (int c = 0; c < 2; c++) g_n[c] = Gp[c][(t + 1) * 32];
        }

        // fc1 (+relu), stage h1; also stage s(t+2) pairs for the A-matvec
#pragma unroll
        for (int c = 0; c < 2; c++) {
            float h1 = a_cur[c] + W1c[i0[c] * 32 + j] + W1c[(8 + i1[c]) * 32 + j] +
                       W1c[(16 + i2[c]) * 32 + j] + W1c[(24 + i3[c]) * 32 + j];
            h1 = fmaxf(h1, 0.0f);
            sts_f32(bxj[c], h1);
            sts_u64(sbj[c], sp_stage[c]);
        }
        // rotate s pipeline + issue LDG for s(t+4)
#pragma unroll
        for (int c = 0; c < 2; c++) {
            sp_stage[c] = sp_next[c];
            sp_next[c] = *(const ull*)(Sp[c] + t4 * 64);
        }
        __syncwarp();

        // fc2 (+relu), stage h2
        float h2v[2];
#pragma unroll
        for (int c = 0; c < 2; c++)
            h2v[c] = fmaxf(matvec32(bx[c], W2p, b2j), 0.0f);
#pragma unroll
        for (int c = 0; c < 2; c++) sts_f32(byj[c], h2v[c]);

        // A[t+2] — recurrence-independent work that fills the stall bubbles
        float a_new[2];
#pragma unroll
        for (int c = 0; c < 2; c++) a_new[c] = matvecA(sb[c], W1p, b1j);
        __syncwarp();

        // fc3 + gumbel (softmax & /tau strictly monotone -> argmax only)
#pragma unroll
        for (int c = 0; c < 2; c++) {
            float v = matvec32(by[c], W3p, b3j) + g_cur[c];

            // per-8-lane-group max: fmax butterfly (exact), then one ballot
            float m = v;
            m = fmaxf(m, __shfl_xor_sync(FULL, m, 4));
            m = fmaxf(m, __shfl_xor_sync(FULL, m, 2));
            m = fmaxf(m, __shfl_xor_sync(FULL, m, 1));
            unsigned bal = __ballot_sync(FULL, v == m);

            int win = __ffs((bal >> gsh) & 0xFFu) - 1;  // lowest lane = first index
            // straight-through forward == exact hard one-hot
            Op[c][t * 32] = (win == jg) ? 1.0f : 0.0f;

            // all 4 group winners from the uniform ballot
            i0[c] = __ffs(bal & 0xFFu) - 1;
            i1[c] = __ffs((bal >> 8) & 0xFFu) - 1;
            i2[c] = __ffs((bal >> 16) & 0xFFu) - 1;
            i3[c] = __ffs((bal >> 24) & 0xFFu) - 1;
        }

        // rotate A pipeline and gumbel
#pragma unroll
        for (int c = 0; c < 2; c++) {
            a_cur[c] = a_n1[c];
            a_n1[c] = a_new[c];
            g_cur[c] = g_n[c];
        }
    }
}

// ============================================================================
// Launch — single fused kernel (precompute GEMM eliminated)
// ============================================================================
extern "C" void kernel_launch(void* const* d_in, const int* in_sizes, int n_in,
                              void* d_out, int out_size) {
    const float* states = (const float*)d_in[0];  // [B,T,64]
    const float* gumbel = (const float*)d_in[1];  // [B,T,4,8]
    // d_in[2] = tau (unused: monotone under argmax)
    const float* W1     = (const float*)d_in[3];  // [96,32]
    const float* b1     = (const float*)d_in[4];  // [32]
    const float* W2     = (const float*)d_in[5];  // [32,32]
    const float* b2     = (const float*)d_in[6];  // [32]
    const float* W3     = (const float*)d_in[7];  // [32,32]
    const float* b3     = (const float*)d_in[8];  // [32]
    float* out = (float*)d_out;                   // [B,T,32]

    recur_fused<<<BB / 4, 64>>>(states, gumbel, W1, b1, W2, b2, W3, b3, out);
}

// round 16
// speedup vs baseline: 1.2803x; 1.2803x over previous
#include <cuda_runtime.h>
#include <cstdint>
#include <cstddef>

typedef unsigned long long ull;

#define BB 4096
#define TT 256
#define DD 64
#define HH 32

// Scratch: A[b,t,j] = b1[j] + states[b,t,:] @ W1[:64,j]   (128 MiB)
__device__ float g_A[(size_t)BB * TT * 32];

// ---------- packed f32x2 helpers ----------
static __device__ __forceinline__ ull pack2(float lo, float hi) {
    ull r;
    asm("mov.b64 %0, {%1, %2};" : "=l"(r) : "f"(lo), "f"(hi));
    return r;
}
static __device__ __forceinline__ void unpack2(ull v, float& lo, float& hi) {
    asm("mov.b64 {%0, %1}, %2;" : "=f"(lo), "=f"(hi) : "l"(v));
}
static __device__ __forceinline__ void ffma2(ull& acc, ull a, ull b) {
    asm("fma.rn.f32x2 %0, %1, %2, %0;" : "+l"(acc) : "l"(a), "l"(b));
}
static __device__ __forceinline__ ull addx2(ull a, ull b) {
    ull r;
    asm("add.rn.f32x2 %0, %1, %2;" : "=l"(r) : "l"(a), "l"(b));
    return r;
}
static __device__ __forceinline__ void lds_v2u64(ull& a, ull& b, uint32_t addr) {
    asm volatile("ld.shared.v2.b64 {%0, %1}, [%2];" : "=l"(a), "=l"(b) : "r"(addr) : "memory");
}
static __device__ __forceinline__ void sts_f32(uint32_t addr, float v) {
    asm volatile("st.shared.f32 [%0], %1;" :: "r"(addr), "f"(v) : "memory");
}
static __device__ __forceinline__ void sts_v4(uint32_t addr, float4 v) {
    asm volatile("st.shared.v4.b32 [%0], {%1, %2, %3, %4};"
                 :: "r"(addr), "f"(v.x), "f"(v.y), "f"(v.z), "f"(v.w) : "memory");
}
static __device__ __forceinline__ uint32_t smem_u32(const void* p) {
    return (uint32_t)__cvta_generic_to_shared(p);
}

// 32-long matvec, h broadcast from smem, 16 packed weight pairs in regs
static __device__ __forceinline__ float matvec32(uint32_t base, const ull* Wp, float bias) {
    ull a0 = 0, a1 = 0, a2 = 0, a3 = 0;
#pragma unroll
    for (int l = 0; l < 8; l++) {
        ull p0, p1;
        lds_v2u64(p0, p1, base + l * 16);
        if (l & 1) {
            ffma2(a2, p0, Wp[2 * l]);
            ffma2(a3, p1, Wp[2 * l + 1]);
        } else {
            ffma2(a0, p0, Wp[2 * l]);
            ffma2(a1, p1, Wp[2 * l + 1]);
        }
    }
    ull s = addx2(addx2(a0, a2), addx2(a1, a3));
    float lo, hi;
    unpack2(s, lo, hi);
    return bias + (lo + hi);
}

// 64-long matvec: s staged in smem as 32 ull k-pairs (broadcast reads),
// 32 packed W1 pairs in registers (phase-1-only live range)
static __device__ __forceinline__ float matvecA(uint32_t base, const ull* W1p, float bias) {
    ull a0 = 0, a1 = 0, a2 = 0, a3 = 0;
#pragma unroll
    for (int l = 0; l < 16; l++) {
        ull p0, p1;
        lds_v2u64(p0, p1, base + l * 16);
        if (l & 1) {
            ffma2(a2, p0, W1p[2 * l]);
            ffma2(a3, p1, W1p[2 * l + 1]);
        } else {
            ffma2(a0, p0, W1p[2 * l]);
            ffma2(a1, p1, W1p[2 * l + 1]);
        }
    }
    ull s = addx2(addx2(a0, a2), addx2(a1, a3));
    float lo, hi;
    unpack2(s, lo, hi);
    return bias + (lo + hi);
}

// ============================================================================
// Fused two-PHASE kernel. Phase 1: each warp computes A for its own 2 chains
// (512 rows) into g_A — W1p registers live ONLY here (R15's mistake was
// keeping them live through the recurrence -> 255 regs, 2 waves). Phase 2:
// the exact R9 recurrence interior (best measured: 257us). No inter-phase
// sync needed: lane j writes g_A[.,j] and later reads g_A[.,j] (same-thread
// program order); the warp's A is hot in L1/L2.
// ============================================================================
__global__ void __launch_bounds__(64) fused_kernel(const float* __restrict__ states,
                                                   const float* __restrict__ gumbel,
                                                   const float* __restrict__ W1,
                                                   const float* __restrict__ b1,
                                                   const float* __restrict__ W2,
                                                   const float* __restrict__ b2,
                                                   const float* __restrict__ W3,
                                                   const float* __restrict__ b3,
                                                   float* __restrict__ out) {
    __shared__ float W1c[32 * 32];                  // rows 64..95 of W1 (phase 2)
    __shared__ __align__(16) ull sbufS[2][8 * 32];  // [warp] 8-row s tile (2 KB)
    __shared__ __align__(16) float bufx[2][2][32];  // [warp][chain] h1
    __shared__ __align__(16) float bufy[2][2][32];  // h2

    int tid = threadIdx.x;
    for (int i = tid; i < 32 * 32; i += 64) W1c[i] = W1[64 * 32 + i];
    __syncthreads();

    const unsigned FULL = 0xffffffffu;
    int w = tid >> 5;
    int j = tid & 31;

    // ======================= PHASE 1: A = s @ W1[:64] + b1 ==================
    {
        ull W1p[32];
#pragma unroll
        for (int i = 0; i < 32; i++)
            W1p[i] = pack2(__ldg(&W1[(2 * i) * 32 + j]), __ldg(&W1[(2 * i + 1) * 32 + j]));
        float b1j = __ldg(&b1[j]);

        uint32_t sbase = smem_u32(&sbufS[w][0]);
        int lrow = j >> 2;                       // staging row owned by lane
        int lseg = j & 3;                        // 16-float segment within row
        uint32_t sdst = sbase + (uint32_t)(lrow * 32 + 8 * lseg) * 8;
        int lidx = lrow * 16 + lseg * 4;         // float4 index within tile

#pragma unroll 1
        for (int c = 0; c < 2; c++) {
            int b = blockIdx.x * 4 + 2 * w + c;
            const float4* S4 = (const float4*)(states + (size_t)b * TT * 64);
            float* Adst = g_A + (size_t)b * TT * 32 + j;

            // prologue: tile 0 into registers
            float4 r0 = S4[lidx], r1 = S4[lidx + 1], r2 = S4[lidx + 2], r3 = S4[lidx + 3];

#pragma unroll 1
            for (int T = 0; T < 32; T++) {       // 32 tiles x 8 rows = 256 rows
                sts_v4(sdst, r0);
                sts_v4(sdst + 16, r1);
                sts_v4(sdst + 32, r2);
                sts_v4(sdst + 48, r3);
                __syncwarp();

                // prefetch next tile (full tile of compute as latency cover)
                int Tn = (T < 31) ? T + 1 : 31;
                int nidx = Tn * 128 + lidx;
                r0 = S4[nidx];
                r1 = S4[nidx + 1];
                r2 = S4[nidx + 2];
                r3 = S4[nidx + 3];

#pragma unroll
                for (int r = 0; r < 8; r++) {
                    float a = matvecA(sbase + (uint32_t)r * 256, W1p, b1j);
                    Adst[(T * 8 + r) * 32] = a;
                }
                __syncwarp();  // WAR: everyone done reading before next stage
            }
        }
    }
    asm volatile("" ::: "memory");  // fence: keep phase-2 weight loads out of phase 1
    __syncwarp();

    // ======================= PHASE 2: exact R9 recurrence ===================
    int jg = j & 7;

    ull W2p[16], W3p[16];
#pragma unroll
    for (int i = 0; i < 16; i++) {
        W2p[i] = pack2(__ldg(&W2[(2 * i) * 32 + j]), __ldg(&W2[(2 * i + 1) * 32 + j]));
        W3p[i] = pack2(__ldg(&W3[(2 * i) * 32 + j]), __ldg(&W3[(2 * i + 1) * 32 + j]));
    }
    float b2j = __ldg(&b2[j]);
    float b3j = __ldg(&b3[j]);

    uint32_t bx[2], by[2], bxj[2], byj[2];
#pragma unroll
    for (int c = 0; c < 2; c++) {
        bx[c] = smem_u32(&bufx[w][c][0]);
        by[c] = smem_u32(&bufy[w][c][0]);
        bxj[c] = bx[c] + 4 * j;
        byj[c] = by[c] + 4 * j;
    }

    const float* Ap[2];
    const float* Gp[2];
    float* Op[2];
    float a_cur[2], g_cur[2];
    int i0[2], i1[2], i2[2], i3[2];

#pragma unroll
    for (int c = 0; c < 2; c++) {
        int b = blockIdx.x * 4 + 2 * w + c;
        size_t base = ((size_t)b * TT) * 32 + j;
        Ap[c] = g_A + base;
        Gp[c] = gumbel + base;
        Op[c] = out + base;
        a_cur[c] = Ap[c][0];
        g_cur[c] = Gp[c][0];
        i0[c] = i1[c] = i2[c] = i3[c] = 0;
    }

#pragma unroll 1
    for (int t = 0; t < TT; t++) {
        // 1-step-ahead prefetch (R9-proven)
        float a_n[2] = {0.f, 0.f}, g_n[2] = {0.f, 0.f};
        if (t + 1 < TT) {
#pragma unroll
            for (int c = 0; c < 2; c++) {
                a_n[c] = Ap[c][(t + 1) * 32];
                g_n[c] = Gp[c][(t + 1) * 32];
            }
        }

        // fc1 (+relu), stage h1
#pragma unroll
        for (int c = 0; c < 2; c++) {
            float h1 = a_cur[c] + W1c[i0[c] * 32 + j] + W1c[(8 + i1[c]) * 32 + j] +
                       W1c[(16 + i2[c]) * 32 + j] + W1c[(24 + i3[c]) * 32 + j];
            h1 = fmaxf(h1, 0.0f);
            sts_f32(bxj[c], h1);
        }
        __syncwarp();

        // fc2 (+relu), stage h2
        float h2v[2];
#pragma unroll
        for (int c = 0; c < 2; c++)
            h2v[c] = fmaxf(matvec32(bx[c], W2p, b2j), 0.0f);
#pragma unroll
        for (int c = 0; c < 2; c++) sts_f32(byj[c], h2v[c]);
        __syncwarp();

        // fc3 + gumbel (softmax & /tau strictly monotone -> argmax only)
        float v[2];
        int ii[2];
#pragma unroll
        for (int c = 0; c < 2; c++) {
            v[c] = matvec32(by[c], W3p, b3j) + g_cur[c];
            ii[c] = jg;
        }

        // per-group-of-8 argmax butterfly, chains interleaved (R9 form)
#pragma unroll
        for (int off = 4; off >= 1; off >>= 1) {
#pragma unroll
            for (int c = 0; c < 2; c++) {
                float ov = __shfl_xor_sync(FULL, v[c], off);
                int oi = __shfl_xor_sync(FULL, ii[c], off);
                if (ov > v[c] || (ov == v[c] && oi < ii[c])) {  // first-index tie-break
                    v[c] = ov;
                    ii[c] = oi;
                }
            }
        }

#pragma unroll
        for (int c = 0; c < 2; c++) {
            // straight-through forward == exact hard one-hot
            Op[c][t * 32] = (ii[c] == jg) ? 1.0f : 0.0f;
            i0[c] = __shfl_sync(FULL, ii[c], 0);
            i1[c] = __shfl_sync(FULL, ii[c], 8);
            i2[c] = __shfl_sync(FULL, ii[c], 16);
            i3[c] = __shfl_sync(FULL, ii[c], 24);
            a_cur[c] = a_n[c];
            g_cur[c] = g_n[c];
        }
    }
}

// ============================================================================
// Launch — single fused kernel
// ============================================================================
extern "C" void kernel_launch(void* const* d_in, const int* in_sizes, int n_in,
                              void* d_out, int out_size) {
    const float* states = (const float*)d_in[0];  // [B,T,64]
    const float* gumbel = (const float*)d_in[1];  // [B,T,4,8]
    // d_in[2] = tau (unused: monotone under argmax)
    const float* W1     = (const float*)d_in[3];  // [96,32]
    const float* b1     = (const float*)d_in[4];  // [32]
    const float* W2     = (const float*)d_in[5];  // [32,32]
    const float* b2     = (const float*)d_in[6];  // [32]
    const float* W3     = (const float*)d_in[7];  // [32,32]
    const float* b3     = (const float*)d_in[8];  // [32]
    float* out = (float*)d_out;                   // [B,T,32]

    fused_kernel<<<BB / 4, 64>>>(states, gumbel, W1, b1, W2, b2, W3, b3, out);
}

// round 17
// speedup vs baseline: 1.3638x; 1.0653x over previous
#include <cuda_runtime.h>
#include <cstdint>
#include <cstddef>

typedef unsigned long long ull;

#define BB 4096
#define TT 256
#define DD 64
#define HH 32
#define BT (BB * TT)

// Scratch: A[b,t,j] = b1[j] + sum_{k<64} states[b,t,k] * W1[k][j]   (128 MiB)
__device__ float g_A[(size_t)BT * 32];

// ---------- packed f32x2 helpers ----------
static __device__ __forceinline__ ull pack2(float lo, float hi) {
    ull r;
    asm("mov.b64 %0, {%1, %2};" : "=l"(r) : "f"(lo), "f"(hi));
    return r;
}
static __device__ __forceinline__ void unpack2(ull v, float& lo, float& hi) {
    asm("mov.b64 {%0, %1}, %2;" : "=f"(lo), "=f"(hi) : "l"(v));
}
static __device__ __forceinline__ void ffma2(ull& acc, ull a, ull b) {
    asm("fma.rn.f32x2 %0, %1, %2, %0;" : "+l"(acc) : "l"(a), "l"(b));
}
static __device__ __forceinline__ ull addx2(ull a, ull b) {
    ull r;
    asm("add.rn.f32x2 %0, %1, %2;" : "=l"(r) : "l"(a), "l"(b));
    return r;
}
static __device__ __forceinline__ void lds_v2u64(ull& a, ull& b, uint32_t addr) {
    asm volatile("ld.shared.v2.b64 {%0, %1}, [%2];" : "=l"(a), "=l"(b) : "r"(addr) : "memory");
}
static __device__ __forceinline__ void sts_f32(uint32_t addr, float v) {
    asm volatile("st.shared.f32 [%0], %1;" :: "r"(addr), "f"(v) : "memory");
}
static __device__ __forceinline__ uint32_t smem_u32(const void* p) {
    return (uint32_t)__cvta_generic_to_shared(p);
}

// ============================================================================
// Kernel 1: A = states @ W1[:64,:] + b1 — EXACT R10 version (measured 175.7us,
// the fastest precompute of the session). 256 thr = 8 warps, 128 rows/block.
// ============================================================================
#define PT_ROWS 128
#define ST 66  // ull stride per k (64 rps + 2 pad)

__global__ void __launch_bounds__(256) precompute_kernel(const float* __restrict__ states,
                                                         const float* __restrict__ W1,
                                                         const float* __restrict__ b1) {
    __shared__ __align__(16) ull stp[64 * ST];
    __shared__ float W1s[64 * 32];

    int tid = threadIdx.x;
    size_t row0 = (size_t)blockIdx.x * PT_ROWS;

    for (int i = tid; i < 64 * 32; i += 256) W1s[i] = W1[i];

    {
        int rp = tid >> 2;
        int ks = tid & 3;
        const float* base = states + (row0 + 2 * (size_t)rp) * 64;
#pragma unroll
        for (int h = 0; h < 4; h++) {
            int k4 = ks + 4 * h;
            float4 fa = *(const float4*)(base + k4 * 4);
            float4 fb = *(const float4*)(base + 64 + k4 * 4);
            stp[(k4 * 4 + 0) * ST + rp] = pack2(fa.x, fb.x);
            stp[(k4 * 4 + 1) * ST + rp] = pack2(fa.y, fb.y);
            stp[(k4 * 4 + 2) * ST + rp] = pack2(fa.z, fb.z);
            stp[(k4 * 4 + 3) * ST + rp] = pack2(fa.w, fb.w);
        }
    }
    __syncthreads();

    int w = tid >> 5;
    int j = tid & 31;

    ull acc[8];
#pragma unroll
    for (int i = 0; i < 8; i++) acc[i] = 0;
    uint32_t stp_base = smem_u32(stp);

#pragma unroll 1
    for (int ch = 0; ch < 2; ch++) {
        ull wd[32];
#pragma unroll
        for (int kk = 0; kk < 32; kk++) {
            float wv = W1s[(32 * ch + kk) * 32 + j];
            wd[kk] = pack2(wv, wv);
        }
#pragma unroll
        for (int kk = 0; kk < 32; kk++) {
            int k = 32 * ch + kk;
            uint32_t a = stp_base + (k * ST + 8 * w) * 8;
            ull p0, p1, p2, p3, p4, p5, p6, p7;
            lds_v2u64(p0, p1, a);
            lds_v2u64(p2, p3, a + 16);
            lds_v2u64(p4, p5, a + 32);
            lds_v2u64(p6, p7, a + 48);
            ffma2(acc[0], p0, wd[kk]);
            ffma2(acc[1], p1, wd[kk]);
            ffma2(acc[2], p2, wd[kk]);
            ffma2(acc[3], p3, wd[kk]);
            ffma2(acc[4], p4, wd[kk]);
            ffma2(acc[5], p5, wd[kk]);
            ffma2(acc[6], p6, wd[kk]);
            ffma2(acc[7], p7, wd[kk]);
        }
    }

    float bj = __ldg(&b1[j]);
    float* gp = g_A + (row0 + 16 * (size_t)w) * 32 + j;
#pragma unroll
    for (int i = 0; i < 8; i++) {
        float lo, hi;
        unpack2(acc[i], lo, hi);
        gp[(2 * i) * 32] = bj + lo;
        gp[(2 * i + 1) * 32] = bj + hi;
    }
}

// ============================================================================
// Kernel 2: recurrence — EXACT R9 version (measured 256.9us, the fastest
// recur of the session; every attempted "improvement" measured slower).
// 2 warps/block, 2 chains/warp, rolled t-loop, 1-step prefetch,
// index-carrying argmax butterfly + 4 broadcast shfls.
// ============================================================================
static __device__ __forceinline__ float matvec32(uint32_t base, const ull* Wp, float bias) {
    ull a0 = 0, a1 = 0, a2 = 0, a3 = 0;
#pragma unroll
    for (int l = 0; l < 8; l++) {
        ull p0, p1;
        lds_v2u64(p0, p1, base + l * 16);
        if (l & 1) {
            ffma2(a2, p0, Wp[2 * l]);
            ffma2(a3, p1, Wp[2 * l + 1]);
        } else {
            ffma2(a0, p0, Wp[2 * l]);
            ffma2(a1, p1, Wp[2 * l + 1]);
        }
    }
    ull s = addx2(addx2(a0, a2), addx2(a1, a3));
    float lo, hi;
    unpack2(s, lo, hi);
    return bias + (lo + hi);
}

__global__ void __launch_bounds__(64) recur_kernel(const float* __restrict__ gumbel,
                                                   const float* __restrict__ W1,
                                                   const float* __restrict__ W2,
                                                   const float* __restrict__ b2,
                                                   const float* __restrict__ W3,
                                                   const float* __restrict__ b3,
                                                   float* __restrict__ out) {
    __shared__ float W1c[32 * 32];                    // rows 64..95 of W1
    __shared__ __align__(16) float bufx[2][2][32];    // [warp][chain][32] : h1
    __shared__ __align__(16) float bufy[2][2][32];    // h2

    int tid = threadIdx.x;
    for (int i = tid; i < 32 * 32; i += 64) W1c[i] = W1[64 * 32 + i];
    __syncthreads();

    const unsigned FULL = 0xffffffffu;
    int w = tid >> 5;
    int j = tid & 31;
    int jg = j & 7;

    ull W2p[16], W3p[16];
#pragma unroll
    for (int i = 0; i < 16; i++) {
        W2p[i] = pack2(__ldg(&W2[(2 * i) * 32 + j]), __ldg(&W2[(2 * i + 1) * 32 + j]));
        W3p[i] = pack2(__ldg(&W3[(2 * i) * 32 + j]), __ldg(&W3[(2 * i + 1) * 32 + j]));
    }
    float b2j = __ldg(&b2[j]);
    float b3j = __ldg(&b3[j]);

    uint32_t bx[2], by[2], bxj[2], byj[2];
#pragma unroll
    for (int c = 0; c < 2; c++) {
        bx[c] = smem_u32(&bufx[w][c][0]);
        by[c] = smem_u32(&bufy[w][c][0]);
        bxj[c] = bx[c] + 4 * j;
        byj[c] = by[c] + 4 * j;
    }

    const float* Ap[2];
    const float* Gp[2];
    float* Op[2];
    float a_cur[2], g_cur[2];
    int i0[2], i1[2], i2[2], i3[2];

#pragma unroll
    for (int c = 0; c < 2; c++) {
        int b = blockIdx.x * 4 + 2 * w + c;
        size_t base = ((size_t)b * TT) * 32 + j;
        Ap[c] = g_A + base;
        Gp[c] = gumbel + base;
        Op[c] = out + base;
        a_cur[c] = Ap[c][0];
        g_cur[c] = Gp[c][0];
        i0[c] = i1[c] = i2[c] = i3[c] = 0;
    }

    for (int t = 0; t < TT; t++) {
        // prefetch next step inputs ahead of the serial chain
        float a_n[2] = {0.f, 0.f}, g_n[2] = {0.f, 0.f};
        if (t + 1 < TT) {
#pragma unroll
            for (int c = 0; c < 2; c++) {
                a_n[c] = Ap[c][(t + 1) * 32];
                g_n[c] = Gp[c][(t + 1) * 32];
            }
        }

        // fc1 (+relu) and stage h1
#pragma unroll
        for (int c = 0; c < 2; c++) {
            float h1 = a_cur[c] + W1c[i0[c] * 32 + j] + W1c[(8 + i1[c]) * 32 + j] +
                       W1c[(16 + i2[c]) * 32 + j] + W1c[(24 + i3[c]) * 32 + j];
            h1 = fmaxf(h1, 0.0f);
            sts_f32(bxj[c], h1);
        }
        __syncwarp();

        // fc2 (+relu), stage h2
        float h2v[2];
#pragma unroll
        for (int c = 0; c < 2; c++)
            h2v[c] = fmaxf(matvec32(bx[c], W2p, b2j), 0.0f);
#pragma unroll
        for (int c = 0; c < 2; c++) sts_f32(byj[c], h2v[c]);
        __syncwarp();

        // fc3, add gumbel (tau/softmax monotone -> argmax only)
        float v[2];
        int ii[2];
#pragma unroll
        for (int c = 0; c < 2; c++) {
            v[c] = matvec32(by[c], W3p, b3j) + g_cur[c];
            ii[c] = jg;
        }

        // per-group argmax butterfly, interleaved across chains
#pragma unroll
        for (int off = 4; off >= 1; off >>= 1) {
#pragma unroll
            for (int c = 0; c < 2; c++) {
                float ov = __shfl_xor_sync(FULL, v[c], off);
                int oi = __shfl_xor_sync(FULL, ii[c], off);
                if (ov > v[c] || (ov == v[c] && oi < ii[c])) {  // first-index tie-break
                    v[c] = ov;
                    ii[c] = oi;
                }
            }
        }

#pragma unroll
        for (int c = 0; c < 2; c++) {
            // straight-through forward == exact hard one-hot
            Op[c][t * 32] = (ii[c] == jg) ? 1.0f : 0.0f;
            i0[c] = __shfl_sync(FULL, ii[c], 0);
            i1[c] = __shfl_sync(FULL, ii[c], 8);
            i2[c] = __shfl_sync(FULL, ii[c], 16);
            i3[c] = __shfl_sync(FULL, ii[c], 24);
            a_cur[c] = a_n[c];
            g_cur[c] = g_n[c];
        }
    }
}

// ============================================================================
// Launch
// ============================================================================
extern "C" void kernel_launch(void* const* d_in, const int* in_sizes, int n_in,
                              void* d_out, int out_size) {
    const float* states = (const float*)d_in[0];  // [B,T,64]
    const float* gumbel = (const float*)d_in[1];  // [B,T,4,8]
    // d_in[2] = tau (unused: monotone under argmax)
    const float* W1     = (const float*)d_in[3];  // [96,32]
    const float* b1     = (const float*)d_in[4];  // [32]
    const float* W2     = (const float*)d_in[5];  // [32,32]
    const float* b2     = (const float*)d_in[6];  // [32]
    const float* W3     = (const float*)d_in[7];  // [32,32]
    const float* b3     = (const float*)d_in[8];  // [32]
    float* out = (float*)d_out;                   // [B,T,32]

    precompute_kernel<<<BT / PT_ROWS, 256>>>(states, W1, b1);
    recur_kernel<<<BB / 4, 64>>>(gumbel, W1, W2, b2, W3, b3, out);
}